// round 14
// baseline (speedup 1.0000x reference)
#include <cuda_runtime.h>
#include <cuda_bf16.h>
#include <math.h>

// ---------------------------------------------------------------------------
//   x [64,2500,1] -> initGCN (rank-1) -> stage1(k=50) -> [64,625,64]
//   stage2(k=25) -> [64,144,64]; stage3(k=12) -> [64,36,64]
//   flatten [64,2304] -> SN-linear(256) -> celu -> SN-linear(256) -> celu
// GEMMs: fma.rn.f32x2 with K-parity lane packing (both operands natively
// packed, no dup movs). Stencils: rolling column sums (6 LDS/node vs 18).
// ---------------------------------------------------------------------------

#define NB 64
#define NC 64

__device__ float g_s [64*2500];
__device__ float g_X1[64*2500*64];
__device__ float g_H [64*2500*64];
__device__ float g_P1[64*625*64];
__device__ float g_P2[64*144*64];
__device__ float g_F [64*36*64];
__device__ float g_G1[256*256];
__device__ float g_G2[256*256];
__device__ float g_Sig[2];
__device__ float g_H1[64*256];
__device__ float g_Par[160];

__device__ __forceinline__ float rdeg(int i, int j, int k) {
    int ci = 1 + (i > 0) + (i < k - 1);
    int cj = 1 + (j > 0) + (j < k - 1);
    return rsqrtf((float)(ci * cj));
}

__device__ __forceinline__ void fma2(unsigned long long& d,
                                     unsigned long long a, unsigned long long b) {
    asm("fma.rn.f32x2 %0, %1, %2, %0;" : "+l"(d) : "l"(a), "l"(b));
}
__device__ __forceinline__ float2 upk2(unsigned long long v) {
    float2 r;
    asm("mov.b64 {%0, %1}, %2;" : "=f"(r.x), "=f"(r.y) : "l"(v));
    return r;
}

// ---------------------------------------------------------------------------
__global__ void k_init_s(const float* __restrict__ x, float* __restrict__ s) {
    int idx = blockIdx.x * 256 + threadIdx.x;
    if (idx >= NB * 2500) return;
    int b = idx / 2500, n = idx - b * 2500;
    int i = n / 50, j = n - i * 50;
    float acc = 0.f;
#pragma unroll
    for (int di = -1; di <= 1; di++)
#pragma unroll
        for (int dj = -1; dj <= 1; dj++) {
            int ii = i + di, jj = j + dj;
            if (ii >= 0 && ii < 50 && jj >= 0 && jj < 50)
                acc += rdeg(ii, jj, 50) * x[b * 2500 + ii * 50 + jj];
        }
    s[idx] = acc * rdeg(i, j, 50);
}

// ---------------------------------------------------------------------------
__global__ void k_prep(const float* __restrict__ w0, const float* __restrict__ b0,
                       const float* __restrict__ W11, const float* __restrict__ b11,
                       float* __restrict__ par) {
    __shared__ float ps[64], qs[64], bs[64];
    int d = threadIdx.x;
    float p = 0.f, q = 0.f;
    for (int c = 0; c < 64; c++) {
        float w = W11[c * 64 + d];
        p = fmaf(w0[c], w, p);
        q = fmaf(b0[c], w, q);
    }
    par[d] = p; par[64 + d] = q;
    ps[d] = p; qs[d] = q; bs[d] = b11[d];
    __syncthreads();
    if (d == 0) {
        float mp = 0, mq = 0, mb = 0, spp = 0, sqq = 0, sbb = 0, spq = 0, spb = 0, sqb = 0;
        for (int c = 0; c < 64; c++) {
            float pp = ps[c], qq = qs[c], bb = bs[c];
            mp += pp; mq += qq; mb += bb;
            spp = fmaf(pp, pp, spp); sqq = fmaf(qq, qq, sqq); sbb = fmaf(bb, bb, sbb);
            spq = fmaf(pp, qq, spq); spb = fmaf(pp, bb, spb); sqb = fmaf(qq, bb, sqb);
        }
        const float inv64 = 1.f / 64.f;
        par[128] = mp * inv64;  par[129] = mq * inv64;  par[130] = mb * inv64;
        par[131] = spp * inv64; par[132] = sqq * inv64; par[133] = sbb * inv64;
        par[134] = spq * inv64; par[135] = spb * inv64; par[136] = sqb * inv64;
    }
}

// ---------------------------------------------------------------------------
__global__ __launch_bounds__(256) void k_x1(const float* __restrict__ s,
                                            const float* __restrict__ par,
                                            const float* __restrict__ b11,
                                            float* __restrict__ out) {
    __shared__ float sh[12 * 12];
    __shared__ float ps[64], qs[64], bs[64], sc[9];
    const int tid = threadIdx.x;
    const int b = blockIdx.z;
    const int ti0 = blockIdx.y * 10, tj0 = blockIdx.x * 10;
    if (tid < 144) {
        int hi = tid / 12, hj = tid - hi * 12;
        int gi = ti0 - 1 + hi, gj = tj0 - 1 + hj;
        float v = 0.f;
        if (gi >= 0 && gi < 50 && gj >= 0 && gj < 50)
            v = s[b * 2500 + gi * 50 + gj];
        sh[tid] = v;
    }
    if (tid < 64) { ps[tid] = par[tid]; qs[tid] = par[64 + tid]; bs[tid] = b11[tid]; }
    else if (tid < 73) sc[tid - 64] = par[128 + tid - 64];
    __syncthreads();

    const int warp = tid >> 5, lane = tid & 31;
    for (int nd = warp; nd < 100; nd += 8) {
        int li = nd / 10, lj = nd - li * 10;
        int gi = ti0 + li, gj = tj0 + lj;
        float T1 = 0.f, T2 = 0.f;
#pragma unroll
        for (int di = 0; di < 3; di++)
#pragma unroll
            for (int dj = 0; dj < 3; dj++) {
                int ii = gi - 1 + di, jj = gj - 1 + dj;
                if (ii >= 0 && ii < 50 && jj >= 0 && jj < 50) {
                    float rr = rdeg(ii, jj, 50);
                    T1 = fmaf(rr, sh[(li + di) * 12 + (lj + dj)], T1);
                    T2 += rr;
                }
            }
        float r = rdeg(gi, gj, 50);
        float al = r * T1, be = r * T2;
        float mean = fmaf(al, sc[0], fmaf(be, sc[1], sc[2]));
        float e2 = al * al * sc[3] + be * be * sc[4] + sc[5]
                 + 2.f * (al * be * sc[6] + al * sc[7] + be * sc[8]);
        float inv = rsqrtf(e2 - mean * mean + 1e-5f);
        const int c0 = lane, c1 = lane + 32;
        float a0 = fmaf(al, ps[c0], fmaf(be, qs[c0], bs[c0]));
        float a1 = fmaf(al, ps[c1], fmaf(be, qs[c1], bs[c1]));
        float y0 = (a0 - mean) * inv;
        float y1 = (a1 - mean) * inv;
        y0 = y0 > 0.f ? y0 : expm1f(y0);
        y1 = y1 > 0.f ? y1 : expm1f(y1);
        float* op = out + ((size_t)b * 2500 + gi * 50 + gj) * 64;
        op[c0] = y0; op[c1] = y1;
    }
}

// ---------------------------------------------------------------------------
// GEMM (FFMA2, K-parity packed): H[m,:] = r(m) * (X[m,:] @ W)
// Tile 256x64, 256 threads, thread = 8 rows x 8 cols.  f32x2 lanes = (k,k+1);
// a-pairs native in row-major Xs, w-pairs native in transposed Wt.
// ---------------------------------------------------------------------------
template<int KSIDE>
__global__ __launch_bounds__(256, 1) void k_gemm3(const float* __restrict__ X,
                                                  const float* __restrict__ W,
                                                  float* __restrict__ H, int M) {
    extern __shared__ float sg[];
    float* Xs = sg;                 // 256 * 68
    float* Wt = sg + 256 * 68;      // 64 * 68, Wt[c][k] = W[k][c]
    const int tid = threadIdx.x;
    const int m0 = blockIdx.x * 256;

    for (int q = tid; q < 1024; q += 256) {
        int k = q >> 4, c4 = (q & 15) * 4;
        float4 wv = ((const float4*)W)[q];
        Wt[(c4 + 0) * 68 + k] = wv.x;
        Wt[(c4 + 1) * 68 + k] = wv.y;
        Wt[(c4 + 2) * 68 + k] = wv.z;
        Wt[(c4 + 3) * 68 + k] = wv.w;
    }
    for (int q = tid; q < 4096; q += 256) {
        int row = q >> 4, part = q & 15;
        int gr = m0 + row;
        float4 v = make_float4(0.f, 0.f, 0.f, 0.f);
        if (gr < M) v = ((const float4*)(X + (size_t)gr * 64))[part];
        *(float4*)(Xs + row * 68 + part * 4) = v;
    }
    __syncthreads();

    const int tx = tid & 7, ty = tid >> 3;
    const int r0 = ty * 8, c0 = tx * 8;
    unsigned long long acc[8][8];
#pragma unroll
    for (int i = 0; i < 8; i++)
#pragma unroll
        for (int j = 0; j < 8; j++) acc[i][j] = 0ULL;

#pragma unroll
    for (int kb = 0; kb < 64; kb += 4) {
        ulonglong2 a[8];
#pragma unroll
        for (int i = 0; i < 8; i++)
            a[i] = *(const ulonglong2*)(Xs + (r0 + i) * 68 + kb);
#pragma unroll
        for (int j = 0; j < 8; j++) {
            ulonglong2 wv = *(const ulonglong2*)(Wt + (c0 + j) * 68 + kb);
#pragma unroll
            for (int i = 0; i < 8; i++) {
                fma2(acc[i][j], a[i].x, wv.x);
                fma2(acc[i][j], a[i].y, wv.y);
            }
        }
    }

    constexpr int KK = KSIDE * KSIDE;
#pragma unroll
    for (int i = 0; i < 8; i++) {
        int gr = m0 + r0 + i;
        if (gr >= M) break;
        int n = gr % KK;
        int gi = n / KSIDE, gj = n - gi * KSIDE;
        float r = rdeg(gi, gj, KSIDE);
        float o[8];
#pragma unroll
        for (int j = 0; j < 8; j++) {
            float2 v = upk2(acc[i][j]);
            o[j] = (v.x + v.y) * r;
        }
        float4* op = (float4*)(H + (size_t)gr * 64 + c0);
        op[0] = make_float4(o[0], o[1], o[2], o[3]);
        op[1] = make_float4(o[4], o[5], o[6], o[7]);
    }
}

// ---------------------------------------------------------------------------
// Stencil with rolling column sums: y = celu(inorm(r*sum3x3(H)+b) [+res]) [pool]
// RESM: 0 none, 1 full residual, 2 rank-1 residual s*w0+b0.
// ---------------------------------------------------------------------------
template<int K, int TI, int TJ, bool POOL, int RESM>
__global__ __launch_bounds__(256) void k_stencil(const float* __restrict__ Hin,
                                                 const float* __restrict__ resid,
                                                 const float* __restrict__ w0,
                                                 const float* __restrict__ b0,
                                                 const float* __restrict__ bias,
                                                 float* __restrict__ out) {
    constexpr int HW = TJ + 2;
    constexpr int HN = (TI + 2) * (TJ + 2);
    constexpr int REG = POOL ? (K / 2) * 2 : K;

    extern __shared__ float sm[];
    float* Bs  = sm;
    float* W0s = sm + 64;
    float* B0s = sm + 128;
    float* Hs  = sm + 192;
    float* Ys  = Hs + HN * 64;

    const int tid = threadIdx.x;
    const int b = blockIdx.z;
    const int ti0 = blockIdx.y * TI, tj0 = blockIdx.x * TJ;
    const size_t inB = (size_t)b * K * K * 64;

    if (tid < 16) ((float4*)Bs)[tid] = ((const float4*)bias)[tid];
    if (RESM == 2) {
        if (tid >= 16 && tid < 32)      ((float4*)W0s)[tid - 16] = ((const float4*)w0)[tid - 16];
        else if (tid >= 32 && tid < 48) ((float4*)B0s)[tid - 32] = ((const float4*)b0)[tid - 32];
    }
    for (int q = tid; q < HN * 16; q += 256) {
        int node = q >> 4, part = q & 15;
        int hi = node / HW, hj = node - hi * HW;
        int gi = ti0 - 1 + hi, gj = tj0 - 1 + hj;
        float4 v = make_float4(0.f, 0.f, 0.f, 0.f);
        if (gi >= 0 && gi < K && gj >= 0 && gj < K)
            v = ((const float4*)(Hin + inB + (size_t)(gi * K + gj) * 64))[part];
        ((float4*)(Hs + node * 64))[part] = v;
    }
    __syncthreads();

    const int warp = tid >> 5, lane = tid & 31;
    const int c0 = lane, c1 = lane + 32;
    for (int li = warp; li < TI; li += 8) {
        int gi = ti0 + li;
        if (gi >= REG) continue;
        const float* h0 = Hs + (li    ) * HW * 64;
        const float* h1 = Hs + (li + 1) * HW * 64;
        const float* h2 = Hs + (li + 2) * HW * 64;
        float s00 = h0[c0] + h1[c0] + h2[c0];
        float s01 = h0[c1] + h1[c1] + h2[c1];
        float s10 = h0[64 + c0] + h1[64 + c0] + h2[64 + c0];
        float s11 = h0[64 + c1] + h1[64 + c1] + h2[64 + c1];
        float s20 = h0[128 + c0] + h1[128 + c0] + h2[128 + c0];
        float s21 = h0[128 + c1] + h1[128 + c1] + h2[128 + c1];
        for (int lj = 0; lj < TJ; lj++) {
            int gj = tj0 + lj;
            float a0 = s00 + s10 + s20;
            float a1 = s01 + s11 + s21;
            s00 = s10; s01 = s11; s10 = s20; s11 = s21;
            if (lj + 1 < TJ) {
                int off = (lj + 3) * 64;
                s20 = h0[off + c0] + h1[off + c0] + h2[off + c0];
                s21 = h0[off + c1] + h1[off + c1] + h2[off + c1];
            }
            if (gj >= REG) continue;
            float r = rdeg(gi, gj, K);
            a0 = fmaf(a0, r, Bs[c0]);
            a1 = fmaf(a1, r, Bs[c1]);
            float sv = a0 + a1, sq = a0 * a0 + a1 * a1;
#pragma unroll
            for (int o = 16; o; o >>= 1) {
                sv += __shfl_xor_sync(0xffffffffu, sv, o);
                sq += __shfl_xor_sync(0xffffffffu, sq, o);
            }
            float mean = sv * (1.f / 64.f);
            float var  = sq * (1.f / 64.f) - mean * mean;
            float inv  = rsqrtf(var + 1e-5f);
            float y0 = (a0 - mean) * inv;
            float y1 = (a1 - mean) * inv;
            if (RESM == 1) {
                const float* rp = resid + inB + (size_t)(gi * K + gj) * 64;
                y0 += rp[c0]; y1 += rp[c1];
            } else if (RESM == 2) {
                float sval = resid[(size_t)b * K * K + gi * K + gj];
                y0 = fmaf(sval, W0s[c0], y0 + B0s[c0]);
                y1 = fmaf(sval, W0s[c1], y1 + B0s[c1]);
            }
            y0 = y0 > 0.f ? y0 : expm1f(y0);
            y1 = y1 > 0.f ? y1 : expm1f(y1);
            if (!POOL) {
                float* op = out + inB + (size_t)(gi * K + gj) * 64;
                op[c0] = y0; op[c1] = y1;
            } else {
                float* yp = Ys + (li * TJ + lj) * 64;
                yp[c0] = y0; yp[c1] = y1;
            }
        }
    }

    if (POOL) {
        __syncthreads();
        constexpr int KP = K / 2;
        constexpr int PT = (TI / 2) * (TJ / 2);
        const size_t outB = (size_t)b * KP * KP * 64;
        for (int q = tid; q < PT * 64; q += 256) {
            int pn = q >> 6, c = q & 63;
            int pi = pn / (TJ / 2), pj = pn - pi * (TJ / 2);
            int li = pi * 2, lj = pj * 2;
            float m0 = fmaxf(Ys[(li * TJ + lj) * 64 + c],
                             Ys[(li * TJ + lj + 1) * 64 + c]);
            float m1 = fmaxf(Ys[((li + 1) * TJ + lj) * 64 + c],
                             Ys[((li + 1) * TJ + lj + 1) * 64 + c]);
            int gpi = ti0 / 2 + pi, gpj = tj0 / 2 + pj;
            out[outB + (size_t)(gpi * KP + gpj) * 64 + c] = fmaxf(m0, m1);
        }
    }
}

// ---------------------------------------------------------------------------
__global__ __launch_bounds__(256) void k_gram(const float* __restrict__ W, int Nf,
                                              float* __restrict__ G) {
    extern __shared__ float sh[];
    float* As = sh;
    float* Bsm = sh + 64 * 130;
    const int tid = threadIdx.x;
    const int j0 = blockIdx.x * 64, i0 = blockIdx.y * 64, k0 = blockIdx.z * 128;
    for (int q = tid; q < 2048; q += 256) {
        int r = q >> 5, c = (q & 31) * 4;
        float4 v = *(const float4*)(W + (size_t)(i0 + r) * Nf + k0 + c);
        As[r * 130 + c] = v.x; As[r * 130 + c + 1] = v.y;
        As[r * 130 + c + 2] = v.z; As[r * 130 + c + 3] = v.w;
        float4 u = *(const float4*)(W + (size_t)(j0 + r) * Nf + k0 + c);
        Bsm[r * 130 + c] = u.x; Bsm[r * 130 + c + 1] = u.y;
        Bsm[r * 130 + c + 2] = u.z; Bsm[r * 130 + c + 3] = u.w;
    }
    __syncthreads();
    const int tx = tid & 15, ty = tid >> 4;
    float acc[4][4];
#pragma unroll
    for (int i = 0; i < 4; i++)
        acc[i][0] = acc[i][1] = acc[i][2] = acc[i][3] = 0.f;
#pragma unroll 4
    for (int k = 0; k < 128; k += 2) {
        float2 a[4], bb[4];
#pragma unroll
        for (int i = 0; i < 4; i++) a[i]  = *(const float2*)(As  + (ty * 4 + i) * 130 + k);
#pragma unroll
        for (int j = 0; j < 4; j++) bb[j] = *(const float2*)(Bsm + (tx * 4 + j) * 130 + k);
#pragma unroll
        for (int i = 0; i < 4; i++)
#pragma unroll
            for (int j = 0; j < 4; j++)
                acc[i][j] = fmaf(a[i].y, bb[j].y, fmaf(a[i].x, bb[j].x, acc[i][j]));
    }
#pragma unroll
    for (int i = 0; i < 4; i++)
#pragma unroll
        for (int j = 0; j < 4; j++)
            atomicAdd(&G[(size_t)(i0 + ty * 4 + i) * 256 + j0 + tx * 4 + j], acc[i][j]);
}

__device__ __forceinline__ float blockReduce1024(float x, float* red) {
#pragma unroll
    for (int o = 16; o; o >>= 1) x += __shfl_xor_sync(0xffffffffu, x, o);
    if ((threadIdx.x & 31) == 0) red[threadIdx.x >> 5] = x;
    __syncthreads();
    float tot = 0.f;
#pragma unroll
    for (int i = 0; i < 32; i++) tot += red[i];
    __syncthreads();
    return tot;
}

// ---------------------------------------------------------------------------
__global__ __launch_bounds__(1024) void k_power(const float* __restrict__ lw1,
                                                const float* __restrict__ lw2,
                                                const float* __restrict__ G1,
                                                const float* __restrict__ G2,
                                                float* __restrict__ sig) {
    const float* G  = blockIdx.x == 0 ? G1 : G2;
    const float* W  = blockIdx.x == 0 ? lw1 : lw2;
    const int   Nf  = blockIdx.x == 0 ? 2304 : 256;
    __shared__ float u[256];
    __shared__ float part[4][256];
    __shared__ float red[32];
    const int tid = threadIdx.x;
    const int row = tid & 255, seg = tid >> 8;
    if (tid < 256) u[tid] = 1.f / 16.f;
    __syncthreads();
    float nz2 = 0.f;
    for (int it = 0; it < 30; it++) {
        const float* gp = G + (size_t)(seg * 64) * 256 + row;
        const float* up = u + seg * 64;
        float a0 = 0.f, a1 = 0.f, a2 = 0.f, a3 = 0.f;
#pragma unroll 4
        for (int j = 0; j < 64; j += 4) {
            a0 = fmaf(gp[(j + 0) * 256], up[j + 0], a0);
            a1 = fmaf(gp[(j + 1) * 256], up[j + 1], a1);
            a2 = fmaf(gp[(j + 2) * 256], up[j + 2], a2);
            a3 = fmaf(gp[(j + 3) * 256], up[j + 3], a3);
        }
        part[seg][row] = (a0 + a1) + (a2 + a3);
        __syncthreads();
        float tot = 0.f;
        if (tid < 256)
            tot = part[0][tid] + part[1][tid] + part[2][tid] + part[3][tid];
        float n2 = blockReduce1024(tot * tot, red);
        if (it == 29) nz2 = n2;
        else if (tid < 256) u[tid] = tot / (sqrtf(n2) + 1e-12f);
        __syncthreads();
    }
    float ss = 0.f;
    for (int j = tid; j < Nf; j += 1024) {
        float acc = 0.f;
#pragma unroll 8
        for (int i = 0; i < 256; i++)
            acc = fmaf(W[(size_t)i * Nf + j], u[i], acc);
        ss += acc * acc;
    }
    float nv2 = blockReduce1024(ss, red);
    if (tid == 0) {
        float t = sqrtf(nz2) / (sqrtf(nv2) + 1e-12f);
        sig[blockIdx.x] = t * t / (t + 1e-12f);
    }
}

// ---------------------------------------------------------------------------
// h1 = celu(F @ W1^T / sigma1 + b1)   grid (4 ogroups, 8 bgroups of 8)
// ---------------------------------------------------------------------------
__global__ __launch_bounds__(256) void k_lin1(const float* __restrict__ F,
                                              const float* __restrict__ W,
                                              const float* __restrict__ bias,
                                              const float* __restrict__ sig,
                                              float* __restrict__ out) {
    extern __shared__ float sl[];
    float* Fs   = sl;               // 8 * 2304
    float* part = sl + 8 * 2304;    // [4][8][64]
    const int tid = threadIdx.x;
    const int og = blockIdx.x, bg = blockIdx.y;
    const float4* src = (const float4*)(F + (size_t)bg * 8 * 2304);
    for (int q = tid; q < 4608; q += 256) ((float4*)Fs)[q] = src[q];
    __syncthreads();
    const int ol = tid & 63, ks = tid >> 6;
    const int o = og * 64 + ol;
    const float4* wr = (const float4*)(W + (size_t)o * 2304 + ks * 576);
    const float* fb = Fs + ks * 576;
    float a[8];
#pragma unroll
    for (int b = 0; b < 8; b++) a[b] = 0.f;
#pragma unroll 2
    for (int k4 = 0; k4 < 144; k4++) {
        float4 w = wr[k4];
#pragma unroll
        for (int b = 0; b < 8; b++) {
            const float* f = fb + b * 2304 + k4 * 4;
            a[b] = fmaf(w.x, f[0], a[b]);
            a[b] = fmaf(w.y, f[1], a[b]);
            a[b] = fmaf(w.z, f[2], a[b]);
            a[b] = fmaf(w.w, f[3], a[b]);
        }
    }
#pragma unroll
    for (int b = 0; b < 8; b++) part[(ks * 8 + b) * 64 + ol] = a[b];
    __syncthreads();
    if (ks == 0) {
        float s0 = sig[0], bo = bias[o];
#pragma unroll
        for (int b = 0; b < 8; b++) {
            float z = part[b * 64 + ol] + part[(8 + b) * 64 + ol]
                    + part[(16 + b) * 64 + ol] + part[(24 + b) * 64 + ol];
            z = z / s0 + bo;
            out[(size_t)(bg * 8 + b) * 256 + o] = z > 0.f ? z : expm1f(z);
        }
    }
}

__global__ void k_lin2(const float* __restrict__ h1, const float* __restrict__ W,
                       const float* __restrict__ bias, const float* __restrict__ sig,
                       float* __restrict__ out) {
    const int b = blockIdx.x, o = threadIdx.x;
    __shared__ float hs[256];
    hs[o] = h1[b * 256 + o];
    __syncthreads();
    const float* wr = W + o * 256;
    float acc = 0.f;
#pragma unroll 8
    for (int k = 0; k < 256; k++) acc = fmaf(wr[k], hs[k], acc);
    acc = acc / sig[1] + bias[o];
    out[b * 256 + o] = acc > 0.f ? acc : expm1f(acc);
}

// ---------------------------------------------------------------------------
extern "C" void kernel_launch(void* const* d_in, const int* in_sizes, int n_in,
                              void* d_out, int out_size) {
    const float* x      = (const float*)d_in[0];
    const float* w_init = (const float*)d_in[1];
    const float* b_init = (const float*)d_in[2];
    const float* w11 = (const float*)d_in[3];  const float* b11 = (const float*)d_in[4];
    const float* w12 = (const float*)d_in[5];  const float* b12 = (const float*)d_in[6];
    const float* w21 = (const float*)d_in[7];  const float* b21 = (const float*)d_in[8];
    const float* w22 = (const float*)d_in[9];  const float* b22 = (const float*)d_in[10];
    const float* w31 = (const float*)d_in[11]; const float* b31 = (const float*)d_in[12];
    const float* w32 = (const float*)d_in[13]; const float* b32 = (const float*)d_in[14];
    const float* lw1 = (const float*)d_in[15]; const float* lb1 = (const float*)d_in[16];
    const float* lw2 = (const float*)d_in[17]; const float* lb2 = (const float*)d_in[18];

    float *pS, *pX1, *pH, *pP1, *pP2, *pF, *pG1, *pG2, *pSig, *pH1, *pPar;
    cudaGetSymbolAddress((void**)&pS,  g_s);
    cudaGetSymbolAddress((void**)&pX1, g_X1);
    cudaGetSymbolAddress((void**)&pH,  g_H);
    cudaGetSymbolAddress((void**)&pP1, g_P1);
    cudaGetSymbolAddress((void**)&pP2, g_P2);
    cudaGetSymbolAddress((void**)&pF,  g_F);
    cudaGetSymbolAddress((void**)&pG1, g_G1);
    cudaGetSymbolAddress((void**)&pG2, g_G2);
    cudaGetSymbolAddress((void**)&pSig, g_Sig);
    cudaGetSymbolAddress((void**)&pH1, g_H1);
    cudaGetSymbolAddress((void**)&pPar, g_Par);

    const size_t sg3 = (256 * 68 + 64 * 68) * sizeof(float);              // 87040
    const size_t sgr = 2 * 64 * 130 * sizeof(float);                      // 66560
    const size_t sl1 = (8 * 2304 + 4 * 8 * 64) * sizeof(float);           // 81920
    const size_t s1b = (192 + 144 * 64 + 100 * 64) * sizeof(float);       // 63232
    const size_t s2a = (192 + 121 * 64) * sizeof(float);                  // 31744
    const size_t s2b = (192 + 100 * 64 + 64 * 64) * sizeof(float);        // 42752
    const size_t s3a = (192 +  64 * 64) * sizeof(float);                  // 17152
    const size_t s3b = (192 +  64 * 64 + 36 * 64) * sizeof(float);        // 26368

    cudaFuncSetAttribute(k_gemm3<50>, cudaFuncAttributeMaxDynamicSharedMemorySize, (int)sg3);
    cudaFuncSetAttribute(k_gemm3<25>, cudaFuncAttributeMaxDynamicSharedMemorySize, (int)sg3);
    cudaFuncSetAttribute(k_gemm3<12>, cudaFuncAttributeMaxDynamicSharedMemorySize, (int)sg3);
    cudaFuncSetAttribute(k_gram,      cudaFuncAttributeMaxDynamicSharedMemorySize, (int)sgr);
    cudaFuncSetAttribute(k_lin1,      cudaFuncAttributeMaxDynamicSharedMemorySize, (int)sl1);
    cudaFuncSetAttribute(k_stencil<50,10,10,true, 2>, cudaFuncAttributeMaxDynamicSharedMemorySize, (int)s1b);
    cudaFuncSetAttribute(k_stencil<25, 9, 9,false,0>, cudaFuncAttributeMaxDynamicSharedMemorySize, (int)s2a);
    cudaFuncSetAttribute(k_stencil<25, 8, 8,true, 1>, cudaFuncAttributeMaxDynamicSharedMemorySize, (int)s2b);
    cudaFuncSetAttribute(k_stencil<12, 6, 6,false,0>, cudaFuncAttributeMaxDynamicSharedMemorySize, (int)s3a);
    cudaFuncSetAttribute(k_stencil<12, 6, 6,true, 1>, cudaFuncAttributeMaxDynamicSharedMemorySize, (int)s3b);

    const int M1 = NB * 2500, M2 = NB * 625, M3 = NB * 144;

    // stage 1 (k=50): rank-1 first GCN
    k_init_s<<<(M1 + 255) / 256, 256>>>(x, pS);
    k_prep<<<1, 64>>>(w_init, b_init, w11, b11, pPar);
    k_x1<<<dim3(5, 5, NB), 256>>>(pS, pPar, b11, pX1);
    k_gemm3<50><<<(M1 + 255) / 256, 256, sg3>>>(pX1, w12, pH, M1);
    k_stencil<50,10,10,true, 2><<<dim3(5,5,NB), 256, s1b>>>(pH, pS, w_init, b_init, b12, pP1);
    // stage 2 (k=25)
    k_gemm3<25><<<(M2 + 255) / 256, 256, sg3>>>(pP1, w21, pH, M2);
    k_stencil<25, 9, 9,false,0><<<dim3(3,3,NB), 256, s2a>>>(pH, nullptr, nullptr, nullptr, b21, pX1);
    k_gemm3<25><<<(M2 + 255) / 256, 256, sg3>>>(pX1, w22, pH, M2);
    k_stencil<25, 8, 8,true, 1><<<dim3(3,3,NB), 256, s2b>>>(pH, pP1, nullptr, nullptr, b22, pP2);
    // stage 3 (k=12)
    k_gemm3<12><<<(M3 + 255) / 256, 256, sg3>>>(pP2, w31, pH, M3);
    k_stencil<12, 6, 6,false,0><<<dim3(2,2,NB), 256, s3a>>>(pH, nullptr, nullptr, nullptr, b31, pX1);
    k_gemm3<12><<<(M3 + 255) / 256, 256, sg3>>>(pX1, w32, pH, M3);
    k_stencil<12, 6, 6,true, 1><<<dim3(2,2,NB), 256, s3b>>>(pH, pP2, nullptr, nullptr, b32, pF);

    // spectral-norm head
    cudaMemsetAsync(pG1, 0, 256 * 256 * sizeof(float));
    cudaMemsetAsync(pG2, 0, 256 * 256 * sizeof(float));
    k_gram<<<dim3(4,4,18), 256, sgr>>>(lw1, 2304, pG1);
    k_gram<<<dim3(4,4, 2), 256, sgr>>>(lw2,  256, pG2);
    k_power<<<2, 1024>>>(lw1, lw2, pG1, pG2, pSig);
    k_lin1<<<dim3(4,8), 256, sl1>>>(pF, lw1, lb1, pSig, pH1);
    k_lin2<<<64, 256>>>(pH1, lw2, lb2, pSig, (float*)d_out);
}

// round 15
// speedup vs baseline: 1.4029x; 1.4029x over previous
#include <cuda_runtime.h>
#include <cuda_bf16.h>
#include <math.h>

// ---------------------------------------------------------------------------
//   x [64,2500,1] -> initGCN (rank-1) -> stage1(k=50) -> [64,625,64]
//   stage2(k=25) -> [64,144,64]; stage3(k=12) -> [64,36,64]
//   flatten [64,2304] -> SN-linear(256) -> celu -> SN-linear(256) -> celu
// GEMM: scalar FFMA, 128x64 tile, 8x4 per thread, float4 k-step-4 inner loop
// (12 LDS.128 per 128 FFMA). Stencils: rolling column sums.
// ---------------------------------------------------------------------------

#define NB 64
#define NC 64

__device__ float g_s [64*2500];
__device__ float g_X1[64*2500*64];
__device__ float g_H [64*2500*64];
__device__ float g_P1[64*625*64];
__device__ float g_P2[64*144*64];
__device__ float g_F [64*36*64];
__device__ float g_G1[256*256];
__device__ float g_G2[256*256];
__device__ float g_Sig[2];
__device__ float g_H1[64*256];
__device__ float g_Par[160];

__device__ __forceinline__ float rdeg(int i, int j, int k) {
    int ci = 1 + (i > 0) + (i < k - 1);
    int cj = 1 + (j > 0) + (j < k - 1);
    return rsqrtf((float)(ci * cj));
}

// ---------------------------------------------------------------------------
__global__ void k_init_s(const float* __restrict__ x, float* __restrict__ s) {
    int idx = blockIdx.x * 256 + threadIdx.x;
    if (idx >= NB * 2500) return;
    int b = idx / 2500, n = idx - b * 2500;
    int i = n / 50, j = n - i * 50;
    float acc = 0.f;
#pragma unroll
    for (int di = -1; di <= 1; di++)
#pragma unroll
        for (int dj = -1; dj <= 1; dj++) {
            int ii = i + di, jj = j + dj;
            if (ii >= 0 && ii < 50 && jj >= 0 && jj < 50)
                acc += rdeg(ii, jj, 50) * x[b * 2500 + ii * 50 + jj];
        }
    s[idx] = acc * rdeg(i, j, 50);
}

// ---------------------------------------------------------------------------
__global__ void k_prep(const float* __restrict__ w0, const float* __restrict__ b0,
                       const float* __restrict__ W11, const float* __restrict__ b11,
                       float* __restrict__ par) {
    __shared__ float ps[64], qs[64], bs[64];
    int d = threadIdx.x;
    float p = 0.f, q = 0.f;
    for (int c = 0; c < 64; c++) {
        float w = W11[c * 64 + d];
        p = fmaf(w0[c], w, p);
        q = fmaf(b0[c], w, q);
    }
    par[d] = p; par[64 + d] = q;
    ps[d] = p; qs[d] = q; bs[d] = b11[d];
    __syncthreads();
    if (d == 0) {
        float mp = 0, mq = 0, mb = 0, spp = 0, sqq = 0, sbb = 0, spq = 0, spb = 0, sqb = 0;
        for (int c = 0; c < 64; c++) {
            float pp = ps[c], qq = qs[c], bb = bs[c];
            mp += pp; mq += qq; mb += bb;
            spp = fmaf(pp, pp, spp); sqq = fmaf(qq, qq, sqq); sbb = fmaf(bb, bb, sbb);
            spq = fmaf(pp, qq, spq); spb = fmaf(pp, bb, spb); sqb = fmaf(qq, bb, sqb);
        }
        const float inv64 = 1.f / 64.f;
        par[128] = mp * inv64;  par[129] = mq * inv64;  par[130] = mb * inv64;
        par[131] = spp * inv64; par[132] = sqq * inv64; par[133] = sbb * inv64;
        par[134] = spq * inv64; par[135] = spb * inv64; par[136] = sqb * inv64;
    }
}

// ---------------------------------------------------------------------------
__global__ __launch_bounds__(256) void k_x1(const float* __restrict__ s,
                                            const float* __restrict__ par,
                                            const float* __restrict__ b11,
                                            float* __restrict__ out) {
    __shared__ float sh[12 * 12];
    __shared__ float ps[64], qs[64], bs[64], sc[9];
    const int tid = threadIdx.x;
    const int b = blockIdx.z;
    const int ti0 = blockIdx.y * 10, tj0 = blockIdx.x * 10;
    if (tid < 144) {
        int hi = tid / 12, hj = tid - hi * 12;
        int gi = ti0 - 1 + hi, gj = tj0 - 1 + hj;
        float v = 0.f;
        if (gi >= 0 && gi < 50 && gj >= 0 && gj < 50)
            v = s[b * 2500 + gi * 50 + gj];
        sh[tid] = v;
    }
    if (tid < 64) { ps[tid] = par[tid]; qs[tid] = par[64 + tid]; bs[tid] = b11[tid]; }
    else if (tid < 73) sc[tid - 64] = par[128 + tid - 64];
    __syncthreads();

    const int warp = tid >> 5, lane = tid & 31;
    for (int nd = warp; nd < 100; nd += 8) {
        int li = nd / 10, lj = nd - li * 10;
        int gi = ti0 + li, gj = tj0 + lj;
        float T1 = 0.f, T2 = 0.f;
#pragma unroll
        for (int di = 0; di < 3; di++)
#pragma unroll
            for (int dj = 0; dj < 3; dj++) {
                int ii = gi - 1 + di, jj = gj - 1 + dj;
                if (ii >= 0 && ii < 50 && jj >= 0 && jj < 50) {
                    float rr = rdeg(ii, jj, 50);
                    T1 = fmaf(rr, sh[(li + di) * 12 + (lj + dj)], T1);
                    T2 += rr;
                }
            }
        float r = rdeg(gi, gj, 50);
        float al = r * T1, be = r * T2;
        float mean = fmaf(al, sc[0], fmaf(be, sc[1], sc[2]));
        float e2 = al * al * sc[3] + be * be * sc[4] + sc[5]
                 + 2.f * (al * be * sc[6] + al * sc[7] + be * sc[8]);
        float inv = rsqrtf(e2 - mean * mean + 1e-5f);
        const int c0 = lane, c1 = lane + 32;
        float a0 = fmaf(al, ps[c0], fmaf(be, qs[c0], bs[c0]));
        float a1 = fmaf(al, ps[c1], fmaf(be, qs[c1], bs[c1]));
        float y0 = (a0 - mean) * inv;
        float y1 = (a1 - mean) * inv;
        y0 = y0 > 0.f ? y0 : expm1f(y0);
        y1 = y1 > 0.f ? y1 : expm1f(y1);
        float* op = out + ((size_t)b * 2500 + gi * 50 + gj) * 64;
        op[c0] = y0; op[c1] = y1;
    }
}

// ---------------------------------------------------------------------------
// GEMM: H[m,:] = r(m) * (X[m,:] @ W).  128x64 tile, 256 threads, 8x4/thread.
// Inner loop: k-step 4, float4 loads both operands (12 LDS.128 / 128 FFMA).
// ---------------------------------------------------------------------------
template<int KSIDE>
__global__ __launch_bounds__(256) void k_gemm4(const float* __restrict__ X,
                                               const float* __restrict__ W,
                                               float* __restrict__ H, int M) {
    extern __shared__ float sg[];
    float* Xs = sg;              // 128*64
    float* Ws = sg + 128 * 64;   // 64*64
    const int tid = threadIdx.x;
    const int m0 = blockIdx.x * 128;

    for (int q = tid; q < 1024; q += 256)
        ((float4*)Ws)[q] = ((const float4*)W)[q];
    for (int q = tid; q < 2048; q += 256) {
        int gr = m0 + (q >> 4);
        float4 v = make_float4(0.f, 0.f, 0.f, 0.f);
        if (gr < M) v = ((const float4*)(X + (size_t)gr * 64))[q & 15];
        ((float4*)Xs)[q] = v;
    }
    __syncthreads();

    const int tx = tid & 15, ty = tid >> 4;
    const int r0 = ty * 8;
    float acc[8][4];
#pragma unroll
    for (int i = 0; i < 8; i++)
        acc[i][0] = acc[i][1] = acc[i][2] = acc[i][3] = 0.f;

    const float4* W4 = (const float4*)Ws;
#pragma unroll 2
    for (int k = 0; k < 64; k += 4) {
        float4 w0 = W4[(k + 0) * 16 + tx];
        float4 w1 = W4[(k + 1) * 16 + tx];
        float4 w2 = W4[(k + 2) * 16 + tx];
        float4 w3 = W4[(k + 3) * 16 + tx];
#pragma unroll
        for (int i = 0; i < 8; i++) {
            float4 a = *(const float4*)(Xs + (r0 + i) * 64 + k);
            acc[i][0] = fmaf(a.x, w0.x, acc[i][0]);
            acc[i][1] = fmaf(a.x, w0.y, acc[i][1]);
            acc[i][2] = fmaf(a.x, w0.z, acc[i][2]);
            acc[i][3] = fmaf(a.x, w0.w, acc[i][3]);
            acc[i][0] = fmaf(a.y, w1.x, acc[i][0]);
            acc[i][1] = fmaf(a.y, w1.y, acc[i][1]);
            acc[i][2] = fmaf(a.y, w1.z, acc[i][2]);
            acc[i][3] = fmaf(a.y, w1.w, acc[i][3]);
            acc[i][0] = fmaf(a.z, w2.x, acc[i][0]);
            acc[i][1] = fmaf(a.z, w2.y, acc[i][1]);
            acc[i][2] = fmaf(a.z, w2.z, acc[i][2]);
            acc[i][3] = fmaf(a.z, w2.w, acc[i][3]);
            acc[i][0] = fmaf(a.w, w3.x, acc[i][0]);
            acc[i][1] = fmaf(a.w, w3.y, acc[i][1]);
            acc[i][2] = fmaf(a.w, w3.z, acc[i][2]);
            acc[i][3] = fmaf(a.w, w3.w, acc[i][3]);
        }
    }

    constexpr int KK = KSIDE * KSIDE;
#pragma unroll
    for (int i = 0; i < 8; i++) {
        int gr = m0 + r0 + i;
        if (gr >= M) break;
        int n = gr % KK;
        int gi = n / KSIDE, gj = n - gi * KSIDE;
        float r = rdeg(gi, gj, KSIDE);
        ((float4*)(H + (size_t)gr * 64))[tx] =
            make_float4(acc[i][0] * r, acc[i][1] * r, acc[i][2] * r, acc[i][3] * r);
    }
}

// ---------------------------------------------------------------------------
// Stencil with rolling column sums.
// RESM: 0 none, 1 full residual, 2 rank-1 residual s*w0+b0.
// ---------------------------------------------------------------------------
template<int K, int TI, int TJ, bool POOL, int RESM>
__global__ __launch_bounds__(256) void k_stencil(const float* __restrict__ Hin,
                                                 const float* __restrict__ resid,
                                                 const float* __restrict__ w0,
                                                 const float* __restrict__ b0,
                                                 const float* __restrict__ bias,
                                                 float* __restrict__ out) {
    constexpr int HW = TJ + 2;
    constexpr int HN = (TI + 2) * (TJ + 2);
    constexpr int REG = POOL ? (K / 2) * 2 : K;

    extern __shared__ float sm[];
    float* Bs  = sm;
    float* W0s = sm + 64;
    float* B0s = sm + 128;
    float* Hs  = sm + 192;
    float* Ys  = Hs + HN * 64;

    const int tid = threadIdx.x;
    const int b = blockIdx.z;
    const int ti0 = blockIdx.y * TI, tj0 = blockIdx.x * TJ;
    const size_t inB = (size_t)b * K * K * 64;

    if (tid < 16) ((float4*)Bs)[tid] = ((const float4*)bias)[tid];
    if (RESM == 2) {
        if (tid >= 16 && tid < 32)      ((float4*)W0s)[tid - 16] = ((const float4*)w0)[tid - 16];
        else if (tid >= 32 && tid < 48) ((float4*)B0s)[tid - 32] = ((const float4*)b0)[tid - 32];
    }
    for (int q = tid; q < HN * 16; q += 256) {
        int node = q >> 4, part = q & 15;
        int hi = node / HW, hj = node - hi * HW;
        int gi = ti0 - 1 + hi, gj = tj0 - 1 + hj;
        float4 v = make_float4(0.f, 0.f, 0.f, 0.f);
        if (gi >= 0 && gi < K && gj >= 0 && gj < K)
            v = ((const float4*)(Hin + inB + (size_t)(gi * K + gj) * 64))[part];
        ((float4*)(Hs + node * 64))[part] = v;
    }
    __syncthreads();

    const int warp = tid >> 5, lane = tid & 31;
    const int c0 = lane, c1 = lane + 32;
    for (int li = warp; li < TI; li += 8) {
        int gi = ti0 + li;
        if (gi >= REG) continue;
        const float* h0 = Hs + (li    ) * HW * 64;
        const float* h1 = Hs + (li + 1) * HW * 64;
        const float* h2 = Hs + (li + 2) * HW * 64;
        float s00 = h0[c0] + h1[c0] + h2[c0];
        float s01 = h0[c1] + h1[c1] + h2[c1];
        float s10 = h0[64 + c0] + h1[64 + c0] + h2[64 + c0];
        float s11 = h0[64 + c1] + h1[64 + c1] + h2[64 + c1];
        float s20 = h0[128 + c0] + h1[128 + c0] + h2[128 + c0];
        float s21 = h0[128 + c1] + h1[128 + c1] + h2[128 + c1];
        for (int lj = 0; lj < TJ; lj++) {
            int gj = tj0 + lj;
            float a0 = s00 + s10 + s20;
            float a1 = s01 + s11 + s21;
            s00 = s10; s01 = s11; s10 = s20; s11 = s21;
            if (lj + 1 < TJ) {
                int off = (lj + 3) * 64;
                s20 = h0[off + c0] + h1[off + c0] + h2[off + c0];
                s21 = h0[off + c1] + h1[off + c1] + h2[off + c1];
            }
            if (gj >= REG) continue;
            float r = rdeg(gi, gj, K);
            a0 = fmaf(a0, r, Bs[c0]);
            a1 = fmaf(a1, r, Bs[c1]);
            float sv = a0 + a1, sq = a0 * a0 + a1 * a1;
#pragma unroll
            for (int o = 16; o; o >>= 1) {
                sv += __shfl_xor_sync(0xffffffffu, sv, o);
                sq += __shfl_xor_sync(0xffffffffu, sq, o);
            }
            float mean = sv * (1.f / 64.f);
            float var  = sq * (1.f / 64.f) - mean * mean;
            float inv  = rsqrtf(var + 1e-5f);
            float y0 = (a0 - mean) * inv;
            float y1 = (a1 - mean) * inv;
            if (RESM == 1) {
                const float* rp = resid + inB + (size_t)(gi * K + gj) * 64;
                y0 += rp[c0]; y1 += rp[c1];
            } else if (RESM == 2) {
                float sval = resid[(size_t)b * K * K + gi * K + gj];
                y0 = fmaf(sval, W0s[c0], y0 + B0s[c0]);
                y1 = fmaf(sval, W0s[c1], y1 + B0s[c1]);
            }
            y0 = y0 > 0.f ? y0 : expm1f(y0);
            y1 = y1 > 0.f ? y1 : expm1f(y1);
            if (!POOL) {
                float* op = out + inB + (size_t)(gi * K + gj) * 64;
                op[c0] = y0; op[c1] = y1;
            } else {
                float* yp = Ys + (li * TJ + lj) * 64;
                yp[c0] = y0; yp[c1] = y1;
            }
        }
    }

    if (POOL) {
        __syncthreads();
        constexpr int KP = K / 2;
        constexpr int PT = (TI / 2) * (TJ / 2);
        const size_t outB = (size_t)b * KP * KP * 64;
        for (int q = tid; q < PT * 64; q += 256) {
            int pn = q >> 6, c = q & 63;
            int pi = pn / (TJ / 2), pj = pn - pi * (TJ / 2);
            int li = pi * 2, lj = pj * 2;
            float m0 = fmaxf(Ys[(li * TJ + lj) * 64 + c],
                             Ys[(li * TJ + lj + 1) * 64 + c]);
            float m1 = fmaxf(Ys[((li + 1) * TJ + lj) * 64 + c],
                             Ys[((li + 1) * TJ + lj + 1) * 64 + c]);
            int gpi = ti0 / 2 + pi, gpj = tj0 / 2 + pj;
            out[outB + (size_t)(gpi * KP + gpj) * 64 + c] = fmaxf(m0, m1);
        }
    }
}

// ---------------------------------------------------------------------------
__global__ __launch_bounds__(256) void k_gram(const float* __restrict__ W, int Nf,
                                              float* __restrict__ G) {
    extern __shared__ float sh[];
    float* As = sh;
    float* Bsm = sh + 64 * 130;
    const int tid = threadIdx.x;
    const int j0 = blockIdx.x * 64, i0 = blockIdx.y * 64, k0 = blockIdx.z * 128;
    for (int q = tid; q < 2048; q += 256) {
        int r = q >> 5, c = (q & 31) * 4;
        float4 v = *(const float4*)(W + (size_t)(i0 + r) * Nf + k0 + c);
        As[r * 130 + c] = v.x; As[r * 130 + c + 1] = v.y;
        As[r * 130 + c + 2] = v.z; As[r * 130 + c + 3] = v.w;
        float4 u = *(const float4*)(W + (size_t)(j0 + r) * Nf + k0 + c);
        Bsm[r * 130 + c] = u.x; Bsm[r * 130 + c + 1] = u.y;
        Bsm[r * 130 + c + 2] = u.z; Bsm[r * 130 + c + 3] = u.w;
    }
    __syncthreads();
    const int tx = tid & 15, ty = tid >> 4;
    float acc[4][4];
#pragma unroll
    for (int i = 0; i < 4; i++)
        acc[i][0] = acc[i][1] = acc[i][2] = acc[i][3] = 0.f;
#pragma unroll 4
    for (int k = 0; k < 128; k += 2) {
        float2 a[4], bb[4];
#pragma unroll
        for (int i = 0; i < 4; i++) a[i]  = *(const float2*)(As  + (ty * 4 + i) * 130 + k);
#pragma unroll
        for (int j = 0; j < 4; j++) bb[j] = *(const float2*)(Bsm + (tx * 4 + j) * 130 + k);
#pragma unroll
        for (int i = 0; i < 4; i++)
#pragma unroll
            for (int j = 0; j < 4; j++)
                acc[i][j] = fmaf(a[i].y, bb[j].y, fmaf(a[i].x, bb[j].x, acc[i][j]));
    }
#pragma unroll
    for (int i = 0; i < 4; i++)
#pragma unroll
        for (int j = 0; j < 4; j++)
            atomicAdd(&G[(size_t)(i0 + ty * 4 + i) * 256 + j0 + tx * 4 + j], acc[i][j]);
}

__device__ __forceinline__ float blockReduce1024(float x, float* red) {
#pragma unroll
    for (int o = 16; o; o >>= 1) x += __shfl_xor_sync(0xffffffffu, x, o);
    if ((threadIdx.x & 31) == 0) red[threadIdx.x >> 5] = x;
    __syncthreads();
    float tot = 0.f;
#pragma unroll
    for (int i = 0; i < 32; i++) tot += red[i];
    __syncthreads();
    return tot;
}

// ---------------------------------------------------------------------------
__global__ __launch_bounds__(1024) void k_power(const float* __restrict__ lw1,
                                                const float* __restrict__ lw2,
                                                const float* __restrict__ G1,
                                                const float* __restrict__ G2,
                                                float* __restrict__ sig) {
    const float* G  = blockIdx.x == 0 ? G1 : G2;
    const float* W  = blockIdx.x == 0 ? lw1 : lw2;
    const int   Nf  = blockIdx.x == 0 ? 2304 : 256;
    __shared__ float u[256];
    __shared__ float part[4][256];
    __shared__ float red[32];
    const int tid = threadIdx.x;
    const int row = tid & 255, seg = tid >> 8;
    if (tid < 256) u[tid] = 1.f / 16.f;
    __syncthreads();
    float nz2 = 0.f;
    for (int it = 0; it < 30; it++) {
        const float* gp = G + (size_t)(seg * 64) * 256 + row;
        const float* up = u + seg * 64;
        float a0 = 0.f, a1 = 0.f, a2 = 0.f, a3 = 0.f;
#pragma unroll 4
        for (int j = 0; j < 64; j += 4) {
            a0 = fmaf(gp[(j + 0) * 256], up[j + 0], a0);
            a1 = fmaf(gp[(j + 1) * 256], up[j + 1], a1);
            a2 = fmaf(gp[(j + 2) * 256], up[j + 2], a2);
            a3 = fmaf(gp[(j + 3) * 256], up[j + 3], a3);
        }
        part[seg][row] = (a0 + a1) + (a2 + a3);
        __syncthreads();
        float tot = 0.f;
        if (tid < 256)
            tot = part[0][tid] + part[1][tid] + part[2][tid] + part[3][tid];
        float n2 = blockReduce1024(tot * tot, red);
        if (it == 29) nz2 = n2;
        else if (tid < 256) u[tid] = tot / (sqrtf(n2) + 1e-12f);
        __syncthreads();
    }
    float ss = 0.f;
    for (int j = tid; j < Nf; j += 1024) {
        float acc = 0.f;
#pragma unroll 8
        for (int i = 0; i < 256; i++)
            acc = fmaf(W[(size_t)i * Nf + j], u[i], acc);
        ss += acc * acc;
    }
    float nv2 = blockReduce1024(ss, red);
    if (tid == 0) {
        float t = sqrtf(nz2) / (sqrtf(nv2) + 1e-12f);
        sig[blockIdx.x] = t * t / (t + 1e-12f);
    }
}

// ---------------------------------------------------------------------------
__global__ __launch_bounds__(256) void k_lin1(const float* __restrict__ F,
                                              const float* __restrict__ W,
                                              const float* __restrict__ bias,
                                              const float* __restrict__ sig,
                                              float* __restrict__ out) {
    extern __shared__ float sl[];
    float* Fs   = sl;               // 8 * 2304
    float* part = sl + 8 * 2304;    // [4][8][64]
    const int tid = threadIdx.x;
    const int og = blockIdx.x, bg = blockIdx.y;
    const float4* src = (const float4*)(F + (size_t)bg * 8 * 2304);
    for (int q = tid; q < 4608; q += 256) ((float4*)Fs)[q] = src[q];
    __syncthreads();
    const int ol = tid & 63, ks = tid >> 6;
    const int o = og * 64 + ol;
    const float4* wr = (const float4*)(W + (size_t)o * 2304 + ks * 576);
    const float* fb = Fs + ks * 576;
    float a[8];
#pragma unroll
    for (int b = 0; b < 8; b++) a[b] = 0.f;
#pragma unroll 2
    for (int k4 = 0; k4 < 144; k4++) {
        float4 w = wr[k4];
#pragma unroll
        for (int b = 0; b < 8; b++) {
            const float* f = fb + b * 2304 + k4 * 4;
            a[b] = fmaf(w.x, f[0], a[b]);
            a[b] = fmaf(w.y, f[1], a[b]);
            a[b] = fmaf(w.z, f[2], a[b]);
            a[b] = fmaf(w.w, f[3], a[b]);
        }
    }
#pragma unroll
    for (int b = 0; b < 8; b++) part[(ks * 8 + b) * 64 + ol] = a[b];
    __syncthreads();
    if (ks == 0) {
        float s0 = sig[0], bo = bias[o];
#pragma unroll
        for (int b = 0; b < 8; b++) {
            float z = part[b * 64 + ol] + part[(8 + b) * 64 + ol]
                    + part[(16 + b) * 64 + ol] + part[(24 + b) * 64 + ol];
            z = z / s0 + bo;
            out[(size_t)(bg * 8 + b) * 256 + o] = z > 0.f ? z : expm1f(z);
        }
    }
}

__global__ void k_lin2(const float* __restrict__ h1, const float* __restrict__ W,
                       const float* __restrict__ bias, const float* __restrict__ sig,
                       float* __restrict__ out) {
    const int b = blockIdx.x, o = threadIdx.x;
    __shared__ float hs[256];
    hs[o] = h1[b * 256 + o];
    __syncthreads();
    const float* wr = W + o * 256;
    float acc = 0.f;
#pragma unroll 8
    for (int k = 0; k < 256; k++) acc = fmaf(wr[k], hs[k], acc);
    acc = acc / sig[1] + bias[o];
    out[b * 256 + o] = acc > 0.f ? acc : expm1f(acc);
}

// ---------------------------------------------------------------------------
extern "C" void kernel_launch(void* const* d_in, const int* in_sizes, int n_in,
                              void* d_out, int out_size) {
    const float* x      = (const float*)d_in[0];
    const float* w_init = (const float*)d_in[1];
    const float* b_init = (const float*)d_in[2];
    const float* w11 = (const float*)d_in[3];  const float* b11 = (const float*)d_in[4];
    const float* w12 = (const float*)d_in[5];  const float* b12 = (const float*)d_in[6];
    const float* w21 = (const float*)d_in[7];  const float* b21 = (const float*)d_in[8];
    const float* w22 = (const float*)d_in[9];  const float* b22 = (const float*)d_in[10];
    const float* w31 = (const float*)d_in[11]; const float* b31 = (const float*)d_in[12];
    const float* w32 = (const float*)d_in[13]; const float* b32 = (const float*)d_in[14];
    const float* lw1 = (const float*)d_in[15]; const float* lb1 = (const float*)d_in[16];
    const float* lw2 = (const float*)d_in[17]; const float* lb2 = (const float*)d_in[18];

    float *pS, *pX1, *pH, *pP1, *pP2, *pF, *pG1, *pG2, *pSig, *pH1, *pPar;
    cudaGetSymbolAddress((void**)&pS,  g_s);
    cudaGetSymbolAddress((void**)&pX1, g_X1);
    cudaGetSymbolAddress((void**)&pH,  g_H);
    cudaGetSymbolAddress((void**)&pP1, g_P1);
    cudaGetSymbolAddress((void**)&pP2, g_P2);
    cudaGetSymbolAddress((void**)&pF,  g_F);
    cudaGetSymbolAddress((void**)&pG1, g_G1);
    cudaGetSymbolAddress((void**)&pG2, g_G2);
    cudaGetSymbolAddress((void**)&pSig, g_Sig);
    cudaGetSymbolAddress((void**)&pH1, g_H1);
    cudaGetSymbolAddress((void**)&pPar, g_Par);

    const size_t sg4 = (128 * 64 + 64 * 64) * sizeof(float);              // 49152
    const size_t sgr = 2 * 64 * 130 * sizeof(float);                      // 66560
    const size_t sl1 = (8 * 2304 + 4 * 8 * 64) * sizeof(float);           // 81920
    const size_t s1b = (192 + 144 * 64 + 100 * 64) * sizeof(float);       // 63232
    const size_t s2a = (192 + 121 * 64) * sizeof(float);                  // 31744
    const size_t s2b = (192 + 100 * 64 + 64 * 64) * sizeof(float);        // 42752
    const size_t s3a = (192 +  64 * 64) * sizeof(float);                  // 17152
    const size_t s3b = (192 +  64 * 64 + 36 * 64) * sizeof(float);        // 26368

    cudaFuncSetAttribute(k_gemm4<50>, cudaFuncAttributeMaxDynamicSharedMemorySize, (int)sg4);
    cudaFuncSetAttribute(k_gemm4<25>, cudaFuncAttributeMaxDynamicSharedMemorySize, (int)sg4);
    cudaFuncSetAttribute(k_gemm4<12>, cudaFuncAttributeMaxDynamicSharedMemorySize, (int)sg4);
    cudaFuncSetAttribute(k_gram,      cudaFuncAttributeMaxDynamicSharedMemorySize, (int)sgr);
    cudaFuncSetAttribute(k_lin1,      cudaFuncAttributeMaxDynamicSharedMemorySize, (int)sl1);
    cudaFuncSetAttribute(k_stencil<50,10,10,true, 2>, cudaFuncAttributeMaxDynamicSharedMemorySize, (int)s1b);
    cudaFuncSetAttribute(k_stencil<25, 9, 9,false,0>, cudaFuncAttributeMaxDynamicSharedMemorySize, (int)s2a);
    cudaFuncSetAttribute(k_stencil<25, 8, 8,true, 1>, cudaFuncAttributeMaxDynamicSharedMemorySize, (int)s2b);
    cudaFuncSetAttribute(k_stencil<12, 6, 6,false,0>, cudaFuncAttributeMaxDynamicSharedMemorySize, (int)s3a);
    cudaFuncSetAttribute(k_stencil<12, 6, 6,true, 1>, cudaFuncAttributeMaxDynamicSharedMemorySize, (int)s3b);

    const int M1 = NB * 2500, M2 = NB * 625, M3 = NB * 144;

    // stage 1 (k=50): rank-1 first GCN
    k_init_s<<<(M1 + 255) / 256, 256>>>(x, pS);
    k_prep<<<1, 64>>>(w_init, b_init, w11, b11, pPar);
    k_x1<<<dim3(5, 5, NB), 256>>>(pS, pPar, b11, pX1);
    k_gemm4<50><<<(M1 + 127) / 128, 256, sg4>>>(pX1, w12, pH, M1);
    k_stencil<50,10,10,true, 2><<<dim3(5,5,NB), 256, s1b>>>(pH, pS, w_init, b_init, b12, pP1);
    // stage 2 (k=25)
    k_gemm4<25><<<(M2 + 127) / 128, 256, sg4>>>(pP1, w21, pH, M2);
    k_stencil<25, 9, 9,false,0><<<dim3(3,3,NB), 256, s2a>>>(pH, nullptr, nullptr, nullptr, b21, pX1);
    k_gemm4<25><<<(M2 + 127) / 128, 256, sg4>>>(pX1, w22, pH, M2);
    k_stencil<25, 8, 8,true, 1><<<dim3(3,3,NB), 256, s2b>>>(pH, pP1, nullptr, nullptr, b22, pP2);
    // stage 3 (k=12)
    k_gemm4<12><<<(M3 + 127) / 128, 256, sg4>>>(pP2, w31, pH, M3);
    k_stencil<12, 6, 6,false,0><<<dim3(2,2,NB), 256, s3a>>>(pH, nullptr, nullptr, nullptr, b31, pX1);
    k_gemm4<12><<<(M3 + 127) / 128, 256, sg4>>>(pX1, w32, pH, M3);
    k_stencil<12, 6, 6,true, 1><<<dim3(2,2,NB), 256, s3b>>>(pH, pP2, nullptr, nullptr, b32, pF);

    // spectral-norm head
    cudaMemsetAsync(pG1, 0, 256 * 256 * sizeof(float));
    cudaMemsetAsync(pG2, 0, 256 * 256 * sizeof(float));
    k_gram<<<dim3(4,4,18), 256, sgr>>>(lw1, 2304, pG1);
    k_gram<<<dim3(4,4, 2), 256, sgr>>>(lw2,  256, pG2);
    k_power<<<2, 1024>>>(lw1, lw2, pG1, pG2, pSig);
    k_lin1<<<dim3(4,8), 256, sl1>>>(pF, lw1, lb1, pSig, pH1);
    k_lin2<<<64, 256>>>(pH1, lw2, lb2, pSig, (float*)d_out);
}

// round 17
// speedup vs baseline: 1.5498x; 1.1047x over previous
#include <cuda_runtime.h>
#include <cuda_bf16.h>
#include <math.h>

// ---------------------------------------------------------------------------
//   x [64,2500,1] -> initGCN (rank-1) -> stage1(k=50) -> [64,625,64]
//   stage2(k=25) -> [64,144,64]; stage3(k=12) -> [64,36,64]
//   flatten [64,2304] -> SN-linear(256) -> celu -> SN-linear(256) -> celu
// Stage-1 x1 is closed-form per node (rank-1 GCN + analytic InstanceNorm), so
// it is synthesized INSIDE the stage-1 GEMM tile (no X1 round-trip).
// GEMMs: 512 threads, 4x4/thread for occupancy. Stencils: rolling column sums.
// R16 fix: __syncthreads() between param-load and row-scalar phases (race).
// ---------------------------------------------------------------------------

#define NB 64
#define NC 64

__device__ float g_s [64*2500];
__device__ float g_X1[64*2500*64];    // stage-2/3 temp
__device__ float g_H [64*2500*64];
__device__ float g_P1[64*625*64];
__device__ float g_P2[64*144*64];
__device__ float g_F [64*36*64];
__device__ float g_G1[256*256];
__device__ float g_G2[256*256];
__device__ float g_Sig[2];
__device__ float g_H1[64*256];
__device__ float g_Par[160];

__device__ __forceinline__ float rdeg(int i, int j, int k) {
    int ci = 1 + (i > 0) + (i < k - 1);
    int cj = 1 + (j > 0) + (j < k - 1);
    return rsqrtf((float)(ci * cj));
}

// ---------------------------------------------------------------------------
__global__ void k_init_s(const float* __restrict__ x, float* __restrict__ s) {
    int idx = blockIdx.x * 256 + threadIdx.x;
    if (idx >= NB * 2500) return;
    int b = idx / 2500, n = idx - b * 2500;
    int i = n / 50, j = n - i * 50;
    float acc = 0.f;
#pragma unroll
    for (int di = -1; di <= 1; di++)
#pragma unroll
        for (int dj = -1; dj <= 1; dj++) {
            int ii = i + di, jj = j + dj;
            if (ii >= 0 && ii < 50 && jj >= 0 && jj < 50)
                acc += rdeg(ii, jj, 50) * x[b * 2500 + ii * 50 + jj];
        }
    s[idx] = acc * rdeg(i, j, 50);
}

// ---------------------------------------------------------------------------
__global__ void k_prep(const float* __restrict__ w0, const float* __restrict__ b0,
                       const float* __restrict__ W11, const float* __restrict__ b11,
                       float* __restrict__ par) {
    __shared__ float ps[64], qs[64], bs[64];
    int d = threadIdx.x;
    float p = 0.f, q = 0.f;
    for (int c = 0; c < 64; c++) {
        float w = W11[c * 64 + d];
        p = fmaf(w0[c], w, p);
        q = fmaf(b0[c], w, q);
    }
    par[d] = p; par[64 + d] = q;
    ps[d] = p; qs[d] = q; bs[d] = b11[d];
    __syncthreads();
    if (d == 0) {
        float mp = 0, mq = 0, mb = 0, spp = 0, sqq = 0, sbb = 0, spq = 0, spb = 0, sqb = 0;
        for (int c = 0; c < 64; c++) {
            float pp = ps[c], qq = qs[c], bb = bs[c];
            mp += pp; mq += qq; mb += bb;
            spp = fmaf(pp, pp, spp); sqq = fmaf(qq, qq, sqq); sbb = fmaf(bb, bb, sbb);
            spq = fmaf(pp, qq, spq); spb = fmaf(pp, bb, spb); sqb = fmaf(qq, bb, sqb);
        }
        const float inv64 = 1.f / 64.f;
        par[128] = mp * inv64;  par[129] = mq * inv64;  par[130] = mb * inv64;
        par[131] = spp * inv64; par[132] = sqq * inv64; par[133] = sbb * inv64;
        par[134] = spq * inv64; par[135] = spb * inv64; par[136] = sqb * inv64;
    }
}

// ---------------------------------------------------------------------------
// Shared GEMM core: acc = Xs[128x64] @ Ws[64x64], 512 thr, 4 rows x 4 cols.
// ---------------------------------------------------------------------------
__device__ __forceinline__ void gemm_core(const float* Xs, const float* Ws,
                                          int tx, int r0, float acc[4][4]) {
#pragma unroll
    for (int i = 0; i < 4; i++)
        acc[i][0] = acc[i][1] = acc[i][2] = acc[i][3] = 0.f;
    const float4* W4 = (const float4*)Ws;
#pragma unroll 4
    for (int k = 0; k < 64; k += 2) {
        float4 w0 = W4[(k    ) * 16 + tx];
        float4 w1 = W4[(k + 1) * 16 + tx];
#pragma unroll
        for (int i = 0; i < 4; i++) {
            float2 a = *(const float2*)(Xs + (r0 + i) * 64 + k);
            acc[i][0] = fmaf(a.x, w0.x, acc[i][0]);
            acc[i][1] = fmaf(a.x, w0.y, acc[i][1]);
            acc[i][2] = fmaf(a.x, w0.z, acc[i][2]);
            acc[i][3] = fmaf(a.x, w0.w, acc[i][3]);
            acc[i][0] = fmaf(a.y, w1.x, acc[i][0]);
            acc[i][1] = fmaf(a.y, w1.y, acc[i][1]);
            acc[i][2] = fmaf(a.y, w1.z, acc[i][2]);
            acc[i][3] = fmaf(a.y, w1.w, acc[i][3]);
        }
    }
}

// ---------------------------------------------------------------------------
// Plain GEMM: H[m,:] = r(m) * (X[m,:] @ W).  128x64 tile, 512 threads.
// ---------------------------------------------------------------------------
template<int KSIDE>
__global__ __launch_bounds__(512) void k_gemm5(const float* __restrict__ X,
                                               const float* __restrict__ W,
                                               float* __restrict__ H, int M) {
    extern __shared__ float sg[];
    float* Xs = sg;              // 128*64
    float* Ws = sg + 128 * 64;   // 64*64
    const int tid = threadIdx.x;
    const int m0 = blockIdx.x * 128;

    for (int q = tid; q < 1024; q += 512)
        ((float4*)Ws)[q] = ((const float4*)W)[q];
    for (int q = tid; q < 2048; q += 512) {
        int gr = m0 + (q >> 4);
        float4 v = make_float4(0.f, 0.f, 0.f, 0.f);
        if (gr < M) v = ((const float4*)(X + (size_t)gr * 64))[q & 15];
        ((float4*)Xs)[q] = v;
    }
    __syncthreads();

    const int tx = tid & 15, ty = tid >> 4;
    const int r0 = ty * 4;
    float acc[4][4];
    gemm_core(Xs, Ws, tx, r0, acc);

    constexpr int KK = KSIDE * KSIDE;
#pragma unroll
    for (int i = 0; i < 4; i++) {
        int gr = m0 + r0 + i;
        if (gr >= M) break;
        int n = gr % KK;
        int gi = n / KSIDE, gj = n - gi * KSIDE;
        float r = rdeg(gi, gj, KSIDE);
        ((float4*)(H + (size_t)gr * 64))[tx] =
            make_float4(acc[i][0] * r, acc[i][1] * r, acc[i][2] * r, acc[i][3] * r);
    }
}

// ---------------------------------------------------------------------------
// Fused stage-1 GEMM: synthesizes X1 tile in smem from s (closed-form x1),
// then H = r(m) * (X1 @ W12).  K=50 grid.
// ---------------------------------------------------------------------------
__global__ __launch_bounds__(512) void k_gemmf(const float* __restrict__ s,
                                               const float* __restrict__ par,
                                               const float* __restrict__ b11,
                                               const float* __restrict__ W,
                                               float* __restrict__ H, int M) {
    extern __shared__ float sg[];
    float* Xs = sg;                   // 128*64
    float* Ws = sg + 128 * 64;        // 64*64
    float* ps = Ws + 64 * 64;         // 64
    float* qs = ps + 64;              // 64
    float* bs = qs + 64;              // 64
    float* sc = bs + 64;              // 9 (padded 16)
    float* sAl = sc + 16;             // 128
    float* sBe = sAl + 128;           // 128
    float* sMe = sBe + 128;           // 128
    float* sIv = sMe + 128;           // 128
    const int tid = threadIdx.x;
    const int m0 = blockIdx.x * 128;

    for (int q = tid; q < 1024; q += 512)
        ((float4*)Ws)[q] = ((const float4*)W)[q];
    if (tid < 64) { ps[tid] = par[tid]; qs[tid] = par[64 + tid]; bs[tid] = b11[tid]; }
    else if (tid >= 64 && tid < 73) sc[tid - 64] = par[128 + tid - 64];
    __syncthreads();   // sc/ps/qs/bs visible to ALL warps before use (R16 fix)

    // per-row scalars (alpha, beta, mean, inv) from s stencil
    if (tid < 128) {
        int gr = m0 + tid;
        float al = 0.f, be = 0.f, mean = 0.f, inv = 0.f;
        if (gr < M) {
            int b = gr / 2500, n = gr - b * 2500;
            int i = n / 50, j = n - i * 50;
            float T1 = 0.f, T2 = 0.f;
#pragma unroll
            for (int di = -1; di <= 1; di++)
#pragma unroll
                for (int dj = -1; dj <= 1; dj++) {
                    int ii = i + di, jj = j + dj;
                    if (ii >= 0 && ii < 50 && jj >= 0 && jj < 50) {
                        float rr = rdeg(ii, jj, 50);
                        T1 = fmaf(rr, s[b * 2500 + ii * 50 + jj], T1);
                        T2 += rr;
                    }
                }
            float r = rdeg(i, j, 50);
            al = r * T1; be = r * T2;
            mean = fmaf(al, sc[0], fmaf(be, sc[1], sc[2]));
            float e2 = al * al * sc[3] + be * be * sc[4] + sc[5]
                     + 2.f * (al * be * sc[6] + al * sc[7] + be * sc[8]);
            inv = rsqrtf(e2 - mean * mean + 1e-5f);
        }
        sAl[tid] = al; sBe[tid] = be; sMe[tid] = mean; sIv[tid] = inv;
    }
    __syncthreads();

    // fill Xs = celu((al*p + be*q + b - mean)*inv); 16 cols per thread
    {
        const int row = tid >> 2, cg = (tid & 3) * 16;
        float al = sAl[row], be = sBe[row], mean = sMe[row], inv = sIv[row];
        float* xr = Xs + row * 64 + cg;
#pragma unroll
        for (int c = 0; c < 16; c++) {
            float v = fmaf(al, ps[cg + c], fmaf(be, qs[cg + c], bs[cg + c]));
            v = (v - mean) * inv;
            xr[c] = v > 0.f ? v : expm1f(v);
        }
    }
    __syncthreads();

    const int tx = tid & 15, ty = tid >> 4;
    const int r0 = ty * 4;
    float acc[4][4];
    gemm_core(Xs, Ws, tx, r0, acc);

#pragma unroll
    for (int i = 0; i < 4; i++) {
        int gr = m0 + r0 + i;
        if (gr >= M) break;
        int n = gr % 2500;
        int gi = n / 50, gj = n - gi * 50;
        float r = rdeg(gi, gj, 50);
        ((float4*)(H + (size_t)gr * 64))[tx] =
            make_float4(acc[i][0] * r, acc[i][1] * r, acc[i][2] * r, acc[i][3] * r);
    }
}

// ---------------------------------------------------------------------------
// Stencil with rolling column sums.
// RESM: 0 none, 1 full residual, 2 rank-1 residual s*w0+b0.
// ---------------------------------------------------------------------------
template<int K, int TI, int TJ, bool POOL, int RESM>
__global__ __launch_bounds__(256) void k_stencil(const float* __restrict__ Hin,
                                                 const float* __restrict__ resid,
                                                 const float* __restrict__ w0,
                                                 const float* __restrict__ b0,
                                                 const float* __restrict__ bias,
                                                 float* __restrict__ out) {
    constexpr int HW = TJ + 2;
    constexpr int HN = (TI + 2) * (TJ + 2);
    constexpr int REG = POOL ? (K / 2) * 2 : K;

    extern __shared__ float sm[];
    float* Bs  = sm;
    float* W0s = sm + 64;
    float* B0s = sm + 128;
    float* Hs  = sm + 192;
    float* Ys  = Hs + HN * 64;

    const int tid = threadIdx.x;
    const int b = blockIdx.z;
    const int ti0 = blockIdx.y * TI, tj0 = blockIdx.x * TJ;
    const size_t inB = (size_t)b * K * K * 64;

    if (tid < 16) ((float4*)Bs)[tid] = ((const float4*)bias)[tid];
    if (RESM == 2) {
        if (tid >= 16 && tid < 32)      ((float4*)W0s)[tid - 16] = ((const float4*)w0)[tid - 16];
        else if (tid >= 32 && tid < 48) ((float4*)B0s)[tid - 32] = ((const float4*)b0)[tid - 32];
    }
    for (int q = tid; q < HN * 16; q += 256) {
        int node = q >> 4, part = q & 15;
        int hi = node / HW, hj = node - hi * HW;
        int gi = ti0 - 1 + hi, gj = tj0 - 1 + hj;
        float4 v = make_float4(0.f, 0.f, 0.f, 0.f);
        if (gi >= 0 && gi < K && gj >= 0 && gj < K)
            v = ((const float4*)(Hin + inB + (size_t)(gi * K + gj) * 64))[part];
        ((float4*)(Hs + node * 64))[part] = v;
    }
    __syncthreads();

    const int warp = tid >> 5, lane = tid & 31;
    const int c0 = lane, c1 = lane + 32;
    for (int li = warp; li < TI; li += 8) {
        int gi = ti0 + li;
        if (gi >= REG) continue;
        const float* h0 = Hs + (li    ) * HW * 64;
        const float* h1 = Hs + (li + 1) * HW * 64;
        const float* h2 = Hs + (li + 2) * HW * 64;
        float s00 = h0[c0] + h1[c0] + h2[c0];
        float s01 = h0[c1] + h1[c1] + h2[c1];
        float s10 = h0[64 + c0] + h1[64 + c0] + h2[64 + c0];
        float s11 = h0[64 + c1] + h1[64 + c1] + h2[64 + c1];
        float s20 = h0[128 + c0] + h1[128 + c0] + h2[128 + c0];
        float s21 = h0[128 + c1] + h1[128 + c1] + h2[128 + c1];
        for (int lj = 0; lj < TJ; lj++) {
            int gj = tj0 + lj;
            float a0 = s00 + s10 + s20;
            float a1 = s01 + s11 + s21;
            s00 = s10; s01 = s11; s10 = s20; s11 = s21;
            if (lj + 1 < TJ) {
                int off = (lj + 3) * 64;
                s20 = h0[off + c0] + h1[off + c0] + h2[off + c0];
                s21 = h0[off + c1] + h1[off + c1] + h2[off + c1];
            }
            if (gj >= REG) continue;
            float r = rdeg(gi, gj, K);
            a0 = fmaf(a0, r, Bs[c0]);
            a1 = fmaf(a1, r, Bs[c1]);
            float sv = a0 + a1, sq = a0 * a0 + a1 * a1;
#pragma unroll
            for (int o = 16; o; o >>= 1) {
                sv += __shfl_xor_sync(0xffffffffu, sv, o);
                sq += __shfl_xor_sync(0xffffffffu, sq, o);
            }
            float mean = sv * (1.f / 64.f);
            float var  = sq * (1.f / 64.f) - mean * mean;
            float inv  = rsqrtf(var + 1e-5f);
            float y0 = (a0 - mean) * inv;
            float y1 = (a1 - mean) * inv;
            if (RESM == 1) {
                const float* rp = resid + inB + (size_t)(gi * K + gj) * 64;
                y0 += rp[c0]; y1 += rp[c1];
            } else if (RESM == 2) {
                float sval = resid[(size_t)b * K * K + gi * K + gj];
                y0 = fmaf(sval, W0s[c0], y0 + B0s[c0]);
                y1 = fmaf(sval, W0s[c1], y1 + B0s[c1]);
            }
            y0 = y0 > 0.f ? y0 : expm1f(y0);
            y1 = y1 > 0.f ? y1 : expm1f(y1);
            if (!POOL) {
                float* op = out + inB + (size_t)(gi * K + gj) * 64;
                op[c0] = y0; op[c1] = y1;
            } else {
                float* yp = Ys + (li * TJ + lj) * 64;
                yp[c0] = y0; yp[c1] = y1;
            }
        }
    }

    if (POOL) {
        __syncthreads();
        constexpr int KP = K / 2;
        constexpr int PT = (TI / 2) * (TJ / 2);
        const size_t outB = (size_t)b * KP * KP * 64;
        for (int q = tid; q < PT * 64; q += 256) {
            int pn = q >> 6, c = q & 63;
            int pi = pn / (TJ / 2), pj = pn - pi * (TJ / 2);
            int li = pi * 2, lj = pj * 2;
            float m0 = fmaxf(Ys[(li * TJ + lj) * 64 + c],
                             Ys[(li * TJ + lj + 1) * 64 + c]);
            float m1 = fmaxf(Ys[((li + 1) * TJ + lj) * 64 + c],
                             Ys[((li + 1) * TJ + lj + 1) * 64 + c]);
            int gpi = ti0 / 2 + pi, gpj = tj0 / 2 + pj;
            out[outB + (size_t)(gpi * KP + gpj) * 64 + c] = fmaxf(m0, m1);
        }
    }
}

// ---------------------------------------------------------------------------
__global__ __launch_bounds__(256) void k_gram(const float* __restrict__ W, int Nf,
                                              float* __restrict__ G) {
    extern __shared__ float sh[];
    float* As = sh;
    float* Bsm = sh + 64 * 130;
    const int tid = threadIdx.x;
    const int j0 = blockIdx.x * 64, i0 = blockIdx.y * 64, k0 = blockIdx.z * 128;
    for (int q = tid; q < 2048; q += 256) {
        int r = q >> 5, c = (q & 31) * 4;
        float4 v = *(const float4*)(W + (size_t)(i0 + r) * Nf + k0 + c);
        As[r * 130 + c] = v.x; As[r * 130 + c + 1] = v.y;
        As[r * 130 + c + 2] = v.z; As[r * 130 + c + 3] = v.w;
        float4 u = *(const float4*)(W + (size_t)(j0 + r) * Nf + k0 + c);
        Bsm[r * 130 + c] = u.x; Bsm[r * 130 + c + 1] = u.y;
        Bsm[r * 130 + c + 2] = u.z; Bsm[r * 130 + c + 3] = u.w;
    }
    __syncthreads();
    const int tx = tid & 15, ty = tid >> 4;
    float acc[4][4];
#pragma unroll
    for (int i = 0; i < 4; i++)
        acc[i][0] = acc[i][1] = acc[i][2] = acc[i][3] = 0.f;
#pragma unroll 4
    for (int k = 0; k < 128; k += 2) {
        float2 a[4], bb[4];
#pragma unroll
        for (int i = 0; i < 4; i++) a[i]  = *(const float2*)(As  + (ty * 4 + i) * 130 + k);
#pragma unroll
        for (int j = 0; j < 4; j++) bb[j] = *(const float2*)(Bsm + (tx * 4 + j) * 130 + k);
#pragma unroll
        for (int i = 0; i < 4; i++)
#pragma unroll
            for (int j = 0; j < 4; j++)
                acc[i][j] = fmaf(a[i].y, bb[j].y, fmaf(a[i].x, bb[j].x, acc[i][j]));
    }
#pragma unroll
    for (int i = 0; i < 4; i++)
#pragma unroll
        for (int j = 0; j < 4; j++)
            atomicAdd(&G[(size_t)(i0 + ty * 4 + i) * 256 + j0 + tx * 4 + j], acc[i][j]);
}

__device__ __forceinline__ float blockReduce1024(float x, float* red) {
#pragma unroll
    for (int o = 16; o; o >>= 1) x += __shfl_xor_sync(0xffffffffu, x, o);
    if ((threadIdx.x & 31) == 0) red[threadIdx.x >> 5] = x;
    __syncthreads();
    float tot = 0.f;
#pragma unroll
    for (int i = 0; i < 32; i++) tot += red[i];
    __syncthreads();
    return tot;
}

// ---------------------------------------------------------------------------
__global__ __launch_bounds__(1024) void k_power(const float* __restrict__ lw1,
                                                const float* __restrict__ lw2,
                                                const float* __restrict__ G1,
                                                const float* __restrict__ G2,
                                                float* __restrict__ sig) {
    const float* G  = blockIdx.x == 0 ? G1 : G2;
    const float* W  = blockIdx.x == 0 ? lw1 : lw2;
    const int   Nf  = blockIdx.x == 0 ? 2304 : 256;
    __shared__ float u[256];
    __shared__ float part[4][256];
    __shared__ float red[32];
    const int tid = threadIdx.x;
    const int row = tid & 255, seg = tid >> 8;
    if (tid < 256) u[tid] = 1.f / 16.f;
    __syncthreads();
    float nz2 = 0.f;
    for (int it = 0; it < 30; it++) {
        const float* gp = G + (size_t)(seg * 64) * 256 + row;
        const float* up = u + seg * 64;
        float a0 = 0.f, a1 = 0.f, a2 = 0.f, a3 = 0.f;
#pragma unroll 4
        for (int j = 0; j < 64; j += 4) {
            a0 = fmaf(gp[(j + 0) * 256], up[j + 0], a0);
            a1 = fmaf(gp[(j + 1) * 256], up[j + 1], a1);
            a2 = fmaf(gp[(j + 2) * 256], up[j + 2], a2);
            a3 = fmaf(gp[(j + 3) * 256], up[j + 3], a3);
        }
        part[seg][row] = (a0 + a1) + (a2 + a3);
        __syncthreads();
        float tot = 0.f;
        if (tid < 256)
            tot = part[0][tid] + part[1][tid] + part[2][tid] + part[3][tid];
        float n2 = blockReduce1024(tot * tot, red);
        if (it == 29) nz2 = n2;
        else if (tid < 256) u[tid] = tot / (sqrtf(n2) + 1e-12f);
        __syncthreads();
    }
    float ss = 0.f;
    for (int j = tid; j < Nf; j += 1024) {
        float acc = 0.f;
#pragma unroll 8
        for (int i = 0; i < 256; i++)
            acc = fmaf(W[(size_t)i * Nf + j], u[i], acc);
        ss += acc * acc;
    }
    float nv2 = blockReduce1024(ss, red);
    if (tid == 0) {
        float t = sqrtf(nz2) / (sqrtf(nv2) + 1e-12f);
        sig[blockIdx.x] = t * t / (t + 1e-12f);
    }
}

// ---------------------------------------------------------------------------
__global__ __launch_bounds__(256) void k_lin1(const float* __restrict__ F,
                                              const float* __restrict__ W,
                                              const float* __restrict__ bias,
                                              const float* __restrict__ sig,
                                              float* __restrict__ out) {
    extern __shared__ float sl[];
    float* Fs   = sl;               // 8 * 2304
    float* part = sl + 8 * 2304;    // [4][8][64]
    const int tid = threadIdx.x;
    const int og = blockIdx.x, bg = blockIdx.y;
    const float4* src = (const float4*)(F + (size_t)bg * 8 * 2304);
    for (int q = tid; q < 4608; q += 256) ((float4*)Fs)[q] = src[q];
    __syncthreads();
    const int ol = tid & 63, ks = tid >> 6;
    const int o = og * 64 + ol;
    const float4* wr = (const float4*)(W + (size_t)o * 2304 + ks * 576);
    const float* fb = Fs + ks * 576;
    float a[8];
#pragma unroll
    for (int b = 0; b < 8; b++) a[b] = 0.f;
#pragma unroll 2
    for (int k4 = 0; k4 < 144; k4++) {
        float4 w = wr[k4];
#pragma unroll
        for (int b = 0; b < 8; b++) {
            const float* f = fb + b * 2304 + k4 * 4;
            a[b] = fmaf(w.x, f[0], a[b]);
            a[b] = fmaf(w.y, f[1], a[b]);
            a[b] = fmaf(w.z, f[2], a[b]);
            a[b] = fmaf(w.w, f[3], a[b]);
        }
    }
#pragma unroll
    for (int b = 0; b < 8; b++) part[(ks * 8 + b) * 64 + ol] = a[b];
    __syncthreads();
    if (ks == 0) {
        float s0 = sig[0], bo = bias[o];
#pragma unroll
        for (int b = 0; b < 8; b++) {
            float z = part[b * 64 + ol] + part[(8 + b) * 64 + ol]
                    + part[(16 + b) * 64 + ol] + part[(24 + b) * 64 + ol];
            z = z / s0 + bo;
            out[(size_t)(bg * 8 + b) * 256 + o] = z > 0.f ? z : expm1f(z);
        }
    }
}

__global__ void k_lin2(const float* __restrict__ h1, const float* __restrict__ W,
                       const float* __restrict__ bias, const float* __restrict__ sig,
                       float* __restrict__ out) {
    const int b = blockIdx.x, o = threadIdx.x;
    __shared__ float hs[256];
    hs[o] = h1[b * 256 + o];
    __syncthreads();
    const float* wr = W + o * 256;
    float acc = 0.f;
#pragma unroll 8
    for (int k = 0; k < 256; k++) acc = fmaf(wr[k], hs[k], acc);
    acc = acc / sig[1] + bias[o];
    out[b * 256 + o] = acc > 0.f ? acc : expm1f(acc);
}

// ---------------------------------------------------------------------------
extern "C" void kernel_launch(void* const* d_in, const int* in_sizes, int n_in,
                              void* d_out, int out_size) {
    const float* x      = (const float*)d_in[0];
    const float* w_init = (const float*)d_in[1];
    const float* b_init = (const float*)d_in[2];
    const float* w11 = (const float*)d_in[3];  const float* b11 = (const float*)d_in[4];
    const float* w12 = (const float*)d_in[5];  const float* b12 = (const float*)d_in[6];
    const float* w21 = (const float*)d_in[7];  const float* b21 = (const float*)d_in[8];
    const float* w22 = (const float*)d_in[9];  const float* b22 = (const float*)d_in[10];
    const float* w31 = (const float*)d_in[11]; const float* b31 = (const float*)d_in[12];
    const float* w32 = (const float*)d_in[13]; const float* b32 = (const float*)d_in[14];
    const float* lw1 = (const float*)d_in[15]; const float* lb1 = (const float*)d_in[16];
    const float* lw2 = (const float*)d_in[17]; const float* lb2 = (const float*)d_in[18];

    float *pS, *pX1, *pH, *pP1, *pP2, *pF, *pG1, *pG2, *pSig, *pH1, *pPar;
    cudaGetSymbolAddress((void**)&pS,  g_s);
    cudaGetSymbolAddress((void**)&pX1, g_X1);
    cudaGetSymbolAddress((void**)&pH,  g_H);
    cudaGetSymbolAddress((void**)&pP1, g_P1);
    cudaGetSymbolAddress((void**)&pP2, g_P2);
    cudaGetSymbolAddress((void**)&pF,  g_F);
    cudaGetSymbolAddress((void**)&pG1, g_G1);
    cudaGetSymbolAddress((void**)&pG2, g_G2);
    cudaGetSymbolAddress((void**)&pSig, g_Sig);
    cudaGetSymbolAddress((void**)&pH1, g_H1);
    cudaGetSymbolAddress((void**)&pPar, g_Par);

    const size_t sg5 = (128 * 64 + 64 * 64) * sizeof(float);              // 49152
    const size_t sgf = sg5 + (3 * 64 + 16 + 4 * 128) * sizeof(float);     // +2880
    const size_t sgr = 2 * 64 * 130 * sizeof(float);                      // 66560
    const size_t sl1 = (8 * 2304 + 4 * 8 * 64) * sizeof(float);           // 81920
    const size_t s1b = (192 + 144 * 64 + 100 * 64) * sizeof(float);       // 63232
    const size_t s2a = (192 + 121 * 64) * sizeof(float);                  // 31744
    const size_t s2b = (192 + 100 * 64 + 64 * 64) * sizeof(float);        // 42752
    const size_t s3a = (192 +  64 * 64) * sizeof(float);                  // 17152
    const size_t s3b = (192 +  64 * 64 + 36 * 64) * sizeof(float);        // 26368

    cudaFuncSetAttribute(k_gemmf,     cudaFuncAttributeMaxDynamicSharedMemorySize, (int)sgf);
    cudaFuncSetAttribute(k_gemm5<25>, cudaFuncAttributeMaxDynamicSharedMemorySize, (int)sg5);
    cudaFuncSetAttribute(k_gemm5<12>, cudaFuncAttributeMaxDynamicSharedMemorySize, (int)sg5);
    cudaFuncSetAttribute(k_gram,      cudaFuncAttributeMaxDynamicSharedMemorySize, (int)sgr);
    cudaFuncSetAttribute(k_lin1,      cudaFuncAttributeMaxDynamicSharedMemorySize, (int)sl1);
    cudaFuncSetAttribute(k_stencil<50,10,10,true, 2>, cudaFuncAttributeMaxDynamicSharedMemorySize, (int)s1b);
    cudaFuncSetAttribute(k_stencil<25, 9, 9,false,0>, cudaFuncAttributeMaxDynamicSharedMemorySize, (int)s2a);
    cudaFuncSetAttribute(k_stencil<25, 8, 8,true, 1>, cudaFuncAttributeMaxDynamicSharedMemorySize, (int)s2b);
    cudaFuncSetAttribute(k_stencil<12, 6, 6,false,0>, cudaFuncAttributeMaxDynamicSharedMemorySize, (int)s3a);
    cudaFuncSetAttribute(k_stencil<12, 6, 6,true, 1>, cudaFuncAttributeMaxDynamicSharedMemorySize, (int)s3b);

    const int M1 = NB * 2500, M2 = NB * 625, M3 = NB * 144;

    // stage 1 (k=50): rank-1 first GCN, x1 fused into GEMM
    k_init_s<<<(M1 + 255) / 256, 256>>>(x, pS);
    k_prep<<<1, 64>>>(w_init, b_init, w11, b11, pPar);
    k_gemmf<<<(M1 + 127) / 128, 512, sgf>>>(pS, pPar, b11, w12, pH, M1);
    k_stencil<50,10,10,true, 2><<<dim3(5,5,NB), 256, s1b>>>(pH, pS, w_init, b_init, b12, pP1);
    // stage 2 (k=25)
    k_gemm5<25><<<(M2 + 127) / 128, 512, sg5>>>(pP1, w21, pH, M2);
    k_stencil<25, 9, 9,false,0><<<dim3(3,3,NB), 256, s2a>>>(pH, nullptr, nullptr, nullptr, b21, pX1);
    k_gemm5<25><<<(M2 + 127) / 128, 512, sg5>>>(pX1, w22, pH, M2);
    k_stencil<25, 8, 8,true, 1><<<dim3(3,3,NB), 256, s2b>>>(pH, pP1, nullptr, nullptr, b22, pP2);
    // stage 3 (k=12)
    k_gemm5<12><<<(M3 + 127) / 128, 512, sg5>>>(pP2, w31, pH, M3);
    k_stencil<12, 6, 6,false,0><<<dim3(2,2,NB), 256, s3a>>>(pH, nullptr, nullptr, nullptr, b31, pX1);
    k_gemm5<12><<<(M3 + 127) / 128, 512, sg5>>>(pX1, w32, pH, M3);
    k_stencil<12, 6, 6,true, 1><<<dim3(2,2,NB), 256, s3b>>>(pH, pP2, nullptr, nullptr, b32, pF);

    // spectral-norm head
    cudaMemsetAsync(pG1, 0, 256 * 256 * sizeof(float));
    cudaMemsetAsync(pG2, 0, 256 * 256 * sizeof(float));
    k_gram<<<dim3(4,4,18), 256, sgr>>>(lw1, 2304, pG1);
    k_gram<<<dim3(4,4, 2), 256, sgr>>>(lw2,  256, pG2);
    k_power<<<2, 1024>>>(lw1, lw2, pG1, pG2, pSig);
    k_lin1<<<dim3(4,8), 256, sl1>>>(pF, lw1, lb1, pSig, pH1);
    k_lin2<<<64, 256>>>(pH1, lw2, lb2, pSig, (float*)d_out);
}